// round 8
// baseline (speedup 1.0000x reference)
#include <cuda_runtime.h>
#include <cuda_fp16.h>
#include <cstdint>
#include <math.h>

#define FILTER_LEN 1024
#define HOP        512
#define CUTOFF     513
#define BATCH      8
#define TLEN       1048576
#define NFRAMES    2049
#define XP_LEN     (TLEN + FILTER_LEN)     // 1049600

#define MROWS   1024                       // interleaved rows: f 0..511 (R,I pairs)
#define BM      128
#define BN      64
#define KC      64                         // fp16 k per chunk (128 B rows)
#define NK      (FILTER_LEN / KC)          // 16

// stage: A(128 rows x 128B) + B(64 rows x 128B); 3 stages
#define SA      0
#define SB      16384
#define STAGE   24576
#define NSTAGE  3
#define DSMEM   (NSTAGE * STAGE)           // 72 KB -> 2 CTAs/SM

#define NREM    (BATCH * (NFRAMES + 512))  // 20488 remainder outputs

// ---------------- device scratch -------------------------------------------
__device__ __align__(128) __half g_xh[(size_t)BATCH * XP_LEN];
__device__ __align__(128) __half g_bh[(size_t)MROWS * FILTER_LEN];

// ---------------- helpers ---------------------------------------------------
__device__ __forceinline__ uint32_t smem_u32(const void* p) {
    uint32_t a;
    asm("{ .reg .u64 t; cvta.to.shared.u64 t, %1; cvt.u32.u64 %0, t; }"
        : "=r"(a) : "l"(p));
    return a;
}
__device__ __forceinline__ void cp_async16(uint32_t dst, const void* src) {
    asm volatile("cp.async.cg.shared.global [%0], [%1], 16;"
                 :: "r"(dst), "l"(src) : "memory");
}
__device__ __forceinline__ void cp_commit() {
    asm volatile("cp.async.commit_group;" ::: "memory");
}
template <int N> __device__ __forceinline__ void cp_wait() {
    asm volatile("cp.async.wait_group %0;" :: "n"(N) : "memory");
}
__device__ __forceinline__ void ldsm_x4(uint32_t& r0, uint32_t& r1,
                                        uint32_t& r2, uint32_t& r3, uint32_t addr) {
    asm volatile("ldmatrix.sync.aligned.m8n8.x4.shared.b16 {%0,%1,%2,%3}, [%4];"
                 : "=r"(r0), "=r"(r1), "=r"(r2), "=r"(r3) : "r"(addr));
}
__device__ __forceinline__ void mma_f16(float* d, const uint32_t* a,
                                        uint32_t b0, uint32_t b1) {
    asm volatile(
        "mma.sync.aligned.m16n8k16.row.col.f32.f16.f16.f32 "
        "{%0,%1,%2,%3}, {%4,%5,%6,%7}, {%8,%9}, {%0,%1,%2,%3};"
        : "+f"(d[0]), "+f"(d[1]), "+f"(d[2]), "+f"(d[3])
        : "r"(a[0]), "r"(a[1]), "r"(a[2]), "r"(a[3]), "r"(b0), "r"(b1));
}
__device__ __forceinline__ uint32_t packh2(float a, float b) {
    __half2 t = __floats2half2_rn(a, b);
    return *reinterpret_cast<uint32_t*>(&t);
}

// ---------------- prep: reflect pad -> fp16 (16 elems/thread) ---------------
__global__ void pad_half_kernel(const float* __restrict__ x) {
    size_t v = (size_t)blockIdx.x * blockDim.x + threadIdx.x;   // 16-elem group
    if (v >= (size_t)BATCH * XP_LEN / 16) return;
    const size_t i0 = v * 16;
    const int b  = (int)(i0 / XP_LEN);
    const int p0 = (int)(i0 % XP_LEN);
    const float* xb = x + (size_t)b * TLEN;
    float e[16];
    #pragma unroll
    for (int q = 0; q < 16; ++q) {
        int j = p0 + q - HOP;
        if (j < 0) j = -j;
        else if (j >= TLEN) j = 2 * TLEN - 2 - j;
        e[q] = xb[j];
    }
    *reinterpret_cast<uint4*>(g_xh + i0) =
        make_uint4(packh2(e[0], e[1]), packh2(e[2], e[3]),
                   packh2(e[4], e[5]), packh2(e[6], e[7]));
    *reinterpret_cast<uint4*>(g_xh + i0 + 8) =
        make_uint4(packh2(e[8], e[9]), packh2(e[10], e[11]),
                   packh2(e[12], e[13]), packh2(e[14], e[15]));
}

// interleave basis rows (2f=real, 2f+1=imag) -> fp16
__global__ void basis_half_kernel(const float* __restrict__ basis) {
    size_t v = (size_t)blockIdx.x * blockDim.x + threadIdx.x;   // 8-elem group
    if (v >= (size_t)MROWS * FILTER_LEN / 8) return;
    const size_t i0 = v * 8;
    const int g = (int)(i0 >> 10);
    const int k = (int)(i0 & 1023);
    const int f = g >> 1;
    const int src = (g & 1) ? (f + CUTOFF) : f;
    const float* bs = basis + (size_t)src * FILTER_LEN + k;
    const float4 f0 = *reinterpret_cast<const float4*>(bs);
    const float4 f1 = *reinterpret_cast<const float4*>(bs + 4);
    *reinterpret_cast<uint4*>(g_bh + i0) =
        make_uint4(packh2(f0.x, f0.y), packh2(f0.z, f0.w),
                   packh2(f1.x, f1.y), packh2(f1.z, f1.w));
}

// ---------------- main: fp16 GEMM (y<8) + fp32 remainder (y==8) -------------
__global__ __launch_bounds__(256, 2)
void stft_mma_kernel(const float* __restrict__ x,
                     const float* __restrict__ basis,
                     const float* __restrict__ eps_p,
                     float* __restrict__ out)
{
    const int tid  = threadIdx.x;
    const int wid  = tid >> 5;
    const int lane = tid & 31;

    // ======== remainder: f=512 row + n=2048 column, exact fp32 =============
    if (blockIdx.y == 8) {
        const float eps = *eps_p;
        const int stride = (int)(gridDim.x * gridDim.z) * 8;
        const int wbase = (int)(blockIdx.z * gridDim.x + blockIdx.x) * 8 + wid;
        for (int o = wbase; o < NREM; o += stride) {
            const int b = o / (NFRAMES + 512);
            const int r = o % (NFRAMES + 512);
            int f, n;
            if (r < NFRAMES) { f = 512; n = r; }
            else             { f = r - NFRAMES; n = 2048; }
            const float* bR = basis + (size_t)f * FILTER_LEN;
            const float* bI = basis + (size_t)(f + CUTOFF) * FILTER_LEN;
            const float* xb = x + (size_t)b * TLEN;
            float aR = 0.f, aI = 0.f;
            #pragma unroll 4
            for (int k = lane; k < FILTER_LEN; k += 32) {
                int j = n * HOP + k - HOP;
                if (j < 0) j = -j;
                else if (j >= TLEN) j = 2 * TLEN - 2 - j;
                const float xv = xb[j];
                aR = fmaf(bR[k], xv, aR);
                aI = fmaf(bI[k], xv, aI);
            }
            #pragma unroll
            for (int s = 16; s; s >>= 1) {
                aR += __shfl_xor_sync(0xffffffffu, aR, s);
                aI += __shfl_xor_sync(0xffffffffu, aI, s);
            }
            if (lane == 0)
                out[((size_t)b * CUTOFF + f) * NFRAMES + n] =
                    sqrtf(fmaf(aR, aR, fmaf(aI, aI, eps)));
        }
        return;
    }

    // ======== dense fp16 GEMM: 128m x 64n tiles, warp 32x32 =================
    extern __shared__ char dsm[];
    const uint32_t sbase = smem_u32(dsm);

    const int b  = blockIdx.z;
    const int m0 = blockIdx.y * BM;
    const int n0 = blockIdx.x * BN;

    const int warp_m = (wid >> 1) * 32;    // 0,32,64,96
    const int warp_n = (wid & 1) * 32;     // 0,32

    // loader geometry: A = 1024 16B chunks (4 rounds), B = 512 (2 rounds)
    int a_row[4], a_c16[4]; uint32_t a_soff[4];
    #pragma unroll
    for (int j = 0; j < 4; ++j) {
        int chunk = tid + j * 256;
        a_row[j] = chunk >> 3;
        a_c16[j] = chunk & 7;
        a_soff[j] = (uint32_t)a_row[j] * 128 + (uint32_t)((a_c16[j] ^ (a_row[j] & 7)) * 16);
    }
    int b_row[2], b_c16[2]; uint32_t b_soff[2];
    #pragma unroll
    for (int j = 0; j < 2; ++j) {
        int chunk = tid + j * 256;
        b_row[j] = chunk >> 3;
        b_c16[j] = chunk & 7;
        b_soff[j] = (uint32_t)b_row[j] * 128 + (uint32_t)((b_c16[j] ^ (b_row[j] & 7)) * 16);
    }

    const __half* bp = g_bh + (size_t)m0 * FILTER_LEN;
    const __half* xp = g_xh + (size_t)b * XP_LEN + (size_t)n0 * HOP;

    float acc[2][4][4];
    #pragma unroll
    for (int mt = 0; mt < 2; ++mt)
        #pragma unroll
        for (int nt = 0; nt < 4; ++nt)
            #pragma unroll
            for (int r = 0; r < 4; ++r) acc[mt][nt][r] = 0.f;

    const int lm_r = lane & 15;
    const int lm_s = lane >> 4;

    auto load_stage = [&](int i) {
        const uint32_t st = sbase + (uint32_t)(i % NSTAGE) * STAGE;
        const int k0 = i * KC;
        #pragma unroll
        for (int j = 0; j < 4; ++j)
            cp_async16(st + SA + a_soff[j],
                       bp + (size_t)a_row[j] * FILTER_LEN + k0 + a_c16[j] * 8);
        #pragma unroll
        for (int j = 0; j < 2; ++j)
            cp_async16(st + SB + b_soff[j],
                       xp + (size_t)b_row[j] * HOP + k0 + b_c16[j] * 8);
        cp_commit();
    };

    load_stage(0);
    load_stage(1);

    for (int i = 0; i < NK; ++i) {
        if (i + 1 < NK) cp_wait<1>(); else cp_wait<0>();
        __syncthreads();                    // stage i ready; all warps past i-1
        if (i + 2 < NK) load_stage(i + 2);  // overwrites buffer (i-1)%3: safe

        const uint32_t st = sbase + (uint32_t)(i % NSTAGE) * STAGE;

        #pragma unroll
        for (int ks = 0; ks < 4; ++ks) {
            const int c16 = ks * 2 + lm_s;
            uint32_t aF[2][4];
            #pragma unroll
            for (int mt = 0; mt < 2; ++mt) {
                const int row = warp_m + mt * 16 + lm_r;
                const uint32_t ad = st + SA + (uint32_t)row * 128
                                  + (uint32_t)((c16 ^ (row & 7)) * 16);
                ldsm_x4(aF[mt][0], aF[mt][1], aF[mt][2], aF[mt][3], ad);
            }
            #pragma unroll
            for (int g = 0; g < 2; ++g) {
                const int row = warp_n + g * 16 + lm_r;
                const uint32_t bd = st + SB + (uint32_t)row * 128
                                  + (uint32_t)((c16 ^ (row & 7)) * 16);
                uint32_t bf[4];
                ldsm_x4(bf[0], bf[1], bf[2], bf[3], bd);
                #pragma unroll
                for (int sub = 0; sub < 2; ++sub) {
                    const int nt = g * 2 + sub;
                    const uint32_t b0 = sub ? bf[1] : bf[0];
                    const uint32_t b1 = sub ? bf[3] : bf[2];
                    #pragma unroll
                    for (int mt = 0; mt < 2; ++mt)
                        mma_f16(acc[mt][nt], aF[mt], b0, b1);
                }
            }
        }
    }

    // ---- epilogue: pair R/I rows via shfl_xor(4), magnitude, store --------
    const float eps = *eps_p;
    const int r4 = lane >> 2;
    const int c2 = (lane & 3) * 2;
    const bool real_holder = ((r4 & 1) == 0);

    #pragma unroll
    for (int mt = 0; mt < 2; ++mt) {
        const int mbase = m0 + warp_m + mt * 16;
        #pragma unroll
        for (int nt = 0; nt < 4; ++nt) {
            float p[4];
            #pragma unroll
            for (int r = 0; r < 4; ++r)
                p[r] = __shfl_xor_sync(0xffffffffu, acc[mt][nt][r], 4);
            if (real_holder) {
                const int nb = n0 + warp_n + nt * 8 + c2;
                const int f0r = (mbase + r4) >> 1;
                const int f1r = (mbase + r4 + 8) >> 1;
                #pragma unroll
                for (int cc = 0; cc < 2; ++cc) {
                    const int n = nb + cc;
                    float re0 = acc[mt][nt][cc],     im0 = p[cc];
                    float re1 = acc[mt][nt][2 + cc], im1 = p[2 + cc];
                    out[((size_t)b * CUTOFF + f0r) * NFRAMES + n] =
                        sqrtf(fmaf(re0, re0, fmaf(im0, im0, eps)));
                    out[((size_t)b * CUTOFF + f1r) * NFRAMES + n] =
                        sqrtf(fmaf(re1, re1, fmaf(im1, im1, eps)));
                }
            }
        }
    }
}

// ---------------- launch ----------------------------------------------------
extern "C" void kernel_launch(void* const* d_in, const int* in_sizes, int n_in,
                              void* d_out, int out_size)
{
    const float* x     = (const float*)d_in[0];
    const float* basis = (const float*)d_in[1];
    const float* eps   = (const float*)d_in[2];
    float* out = (float*)d_out;

    {
        size_t tot = (size_t)BATCH * XP_LEN / 16;
        pad_half_kernel<<<(unsigned)((tot + 255) / 256), 256>>>(x);
    }
    {
        size_t tot = (size_t)MROWS * FILTER_LEN / 8;
        basis_half_kernel<<<(unsigned)((tot + 255) / 256), 256>>>(basis);
    }
    {
        cudaFuncSetAttribute(stft_mma_kernel,
                             cudaFuncAttributeMaxDynamicSharedMemorySize, DSMEM);
        dim3 grid(32, 9, BATCH);     // y<8: dense GEMM; y==8: fp32 remainder
        stft_mma_kernel<<<grid, 256, DSMEM>>>(x, basis, eps, out);
    }
}

// round 9
// speedup vs baseline: 1.1144x; 1.1144x over previous
#include <cuda_runtime.h>
#include <cuda_fp16.h>
#include <cstdint>
#include <math.h>

#define FILTER_LEN 1024
#define HOP        512
#define CUTOFF     513
#define BATCH      8
#define TLEN       1048576
#define NFRAMES    2049
#define XP_LEN     (TLEN + FILTER_LEN)     // 1049600

#define MROWS   1024                       // interleaved rows: f 0..511 (R,I pairs)
#define BM      128
#define BN      128
#define KC      64                         // fp16 k per chunk (128 B rows)
#define NK      (FILTER_LEN / KC)          // 16

// stage: A(128 rows x 128B) + B(128 rows x 128B); 3 stages, 2 CTAs/SM
#define SA      0
#define SB      16384
#define STAGE   32768
#define NSTAGE  3
#define DSMEM   (NSTAGE * STAGE)           // 96 KB/CTA -> 192 KB/SM

#define NREM    (BATCH * (NFRAMES + 512))  // 20488 remainder outputs

// ---------------- device scratch -------------------------------------------
__device__ __align__(128) __half g_xh[(size_t)BATCH * XP_LEN];
__device__ __align__(128) __half g_bh[(size_t)MROWS * FILTER_LEN];

// ---------------- helpers ---------------------------------------------------
__device__ __forceinline__ uint32_t smem_u32(const void* p) {
    uint32_t a;
    asm("{ .reg .u64 t; cvta.to.shared.u64 t, %1; cvt.u32.u64 %0, t; }"
        : "=r"(a) : "l"(p));
    return a;
}
__device__ __forceinline__ void cp_async16(uint32_t dst, const void* src) {
    asm volatile("cp.async.cg.shared.global [%0], [%1], 16;"
                 :: "r"(dst), "l"(src) : "memory");
}
__device__ __forceinline__ void cp_commit() {
    asm volatile("cp.async.commit_group;" ::: "memory");
}
template <int N> __device__ __forceinline__ void cp_wait() {
    asm volatile("cp.async.wait_group %0;" :: "n"(N) : "memory");
}
__device__ __forceinline__ void ldsm_x4(uint32_t& r0, uint32_t& r1,
                                        uint32_t& r2, uint32_t& r3, uint32_t addr) {
    asm volatile("ldmatrix.sync.aligned.m8n8.x4.shared.b16 {%0,%1,%2,%3}, [%4];"
                 : "=r"(r0), "=r"(r1), "=r"(r2), "=r"(r3) : "r"(addr));
}
__device__ __forceinline__ void mma_f16(float* d, const uint32_t* a,
                                        uint32_t b0, uint32_t b1) {
    asm volatile(
        "mma.sync.aligned.m16n8k16.row.col.f32.f16.f16.f32 "
        "{%0,%1,%2,%3}, {%4,%5,%6,%7}, {%8,%9}, {%0,%1,%2,%3};"
        : "+f"(d[0]), "+f"(d[1]), "+f"(d[2]), "+f"(d[3])
        : "r"(a[0]), "r"(a[1]), "r"(a[2]), "r"(a[3]), "r"(b0), "r"(b1));
}
__device__ __forceinline__ uint32_t packh2(float a, float b) {
    __half2 t = __floats2half2_rn(a, b);
    return *reinterpret_cast<uint32_t*>(&t);
}

// ---------------- prep: reflect pad -> fp16 (8 elems/thread) ----------------
__global__ void pad_half_kernel(const float* __restrict__ x) {
    size_t v = (size_t)blockIdx.x * blockDim.x + threadIdx.x;   // 8-elem group
    if (v >= (size_t)BATCH * XP_LEN / 8) return;
    const size_t i0 = v * 8;
    const int b  = (int)(i0 / XP_LEN);
    const int p0 = (int)(i0 % XP_LEN);
    const float* xb = x + (size_t)b * TLEN;
    float e[8];
    #pragma unroll
    for (int q = 0; q < 8; ++q) {
        int j = p0 + q - HOP;
        if (j < 0) j = -j;
        else if (j >= TLEN) j = 2 * TLEN - 2 - j;
        e[q] = xb[j];
    }
    *reinterpret_cast<uint4*>(g_xh + i0) =
        make_uint4(packh2(e[0], e[1]), packh2(e[2], e[3]),
                   packh2(e[4], e[5]), packh2(e[6], e[7]));
}

// interleave basis rows (2f=real, 2f+1=imag) -> fp16
__global__ void basis_half_kernel(const float* __restrict__ basis) {
    size_t v = (size_t)blockIdx.x * blockDim.x + threadIdx.x;   // 8-elem group
    if (v >= (size_t)MROWS * FILTER_LEN / 8) return;
    const size_t i0 = v * 8;
    const int g = (int)(i0 >> 10);
    const int k = (int)(i0 & 1023);
    const int f = g >> 1;
    const int src = (g & 1) ? (f + CUTOFF) : f;
    const float* bs = basis + (size_t)src * FILTER_LEN + k;
    const float4 f0 = *reinterpret_cast<const float4*>(bs);
    const float4 f1 = *reinterpret_cast<const float4*>(bs + 4);
    *reinterpret_cast<uint4*>(g_bh + i0) =
        make_uint4(packh2(f0.x, f0.y), packh2(f0.z, f0.w),
                   packh2(f1.x, f1.y), packh2(f1.z, f1.w));
}

// ---------------- main: fp16 GEMM (y<8) + fp32 remainder (y==8) -------------
__global__ __launch_bounds__(128, 2)
void stft_mma_kernel(const float* __restrict__ x,
                     const float* __restrict__ basis,
                     const float* __restrict__ eps_p,
                     float* __restrict__ out)
{
    const int tid  = threadIdx.x;
    const int wid  = tid >> 5;
    const int lane = tid & 31;

    // ======== remainder: f=512 row + n=2048 column, exact fp32 =============
    if (blockIdx.y == 8) {
        const float eps = *eps_p;
        const int stride = (int)(gridDim.x * gridDim.z) * 4;
        const int wbase = (int)(blockIdx.z * gridDim.x + blockIdx.x) * 4 + wid;
        for (int o = wbase; o < NREM; o += stride) {
            const int b = o / (NFRAMES + 512);
            const int r = o % (NFRAMES + 512);
            int f, n;
            if (r < NFRAMES) { f = 512; n = r; }
            else             { f = r - NFRAMES; n = 2048; }
            const float* bR = basis + (size_t)f * FILTER_LEN;
            const float* bI = basis + (size_t)(f + CUTOFF) * FILTER_LEN;
            const float* xb = x + (size_t)b * TLEN;
            float aR = 0.f, aI = 0.f;
            #pragma unroll 4
            for (int k = lane; k < FILTER_LEN; k += 32) {
                int j = n * HOP + k - HOP;
                if (j < 0) j = -j;
                else if (j >= TLEN) j = 2 * TLEN - 2 - j;
                const float xv = xb[j];
                aR = fmaf(bR[k], xv, aR);
                aI = fmaf(bI[k], xv, aI);
            }
            #pragma unroll
            for (int s = 16; s; s >>= 1) {
                aR += __shfl_xor_sync(0xffffffffu, aR, s);
                aI += __shfl_xor_sync(0xffffffffu, aI, s);
            }
            if (lane == 0)
                out[((size_t)b * CUTOFF + f) * NFRAMES + n] =
                    sqrtf(fmaf(aR, aR, fmaf(aI, aI, eps)));
        }
        return;
    }

    // ======== dense fp16 GEMM: 128m x 128n tiles, 4 warps, warp 64x64 ======
    extern __shared__ char dsm[];
    const uint32_t sbase = smem_u32(dsm);

    const int b  = blockIdx.z;
    const int m0 = blockIdx.y * BM;
    const int n0 = blockIdx.x * BN;

    const int warp_m = (wid >> 1) * 64;    // 0,64
    const int warp_n = (wid & 1) * 64;     // 0,64

    // loader geometry: 128 threads; A/B each 1024 16B chunks -> 8 rounds
    const int l_row0 = tid >> 3;           // 0..15
    const int l_c16  = tid & 7;
    const uint32_t l_soff0 = (uint32_t)l_row0 * 128
                           + (uint32_t)((l_c16 ^ (l_row0 & 7)) * 16);

    const __half* bp = g_bh + (size_t)m0 * FILTER_LEN;
    const __half* xp = g_xh + (size_t)b * XP_LEN + (size_t)n0 * HOP;
    const __half* agp = bp + (size_t)l_row0 * FILTER_LEN + l_c16 * 8;
    const __half* bgp = xp + (size_t)l_row0 * HOP + l_c16 * 8;

    float acc[4][8][4];
    #pragma unroll
    for (int mt = 0; mt < 4; ++mt)
        #pragma unroll
        for (int nt = 0; nt < 8; ++nt)
            #pragma unroll
            for (int r = 0; r < 4; ++r) acc[mt][nt][r] = 0.f;

    const int lm_r = lane & 15;
    const int lm_s = lane >> 4;

    auto load_stage = [&](int i) {
        const uint32_t st = sbase + (uint32_t)(i % NSTAGE) * STAGE;
        const int k0 = i * KC;
        #pragma unroll
        for (int j = 0; j < 8; ++j) {
            // row step 16 keeps (row&7) invariant -> swizzle offset constant
            cp_async16(st + SA + l_soff0 + (uint32_t)j * 2048,
                       agp + (size_t)j * 16 * FILTER_LEN + k0);
            cp_async16(st + SB + l_soff0 + (uint32_t)j * 2048,
                       bgp + (size_t)j * 16 * HOP + k0);
        }
        cp_commit();
    };

    load_stage(0);
    load_stage(1);

    for (int i = 0; i < NK; ++i) {
        if (i + 1 < NK) cp_wait<1>(); else cp_wait<0>();
        __syncthreads();                    // stage i ready; all warps past i-1
        if (i + 2 < NK) load_stage(i + 2);  // overwrites buffer (i-1)%3: safe

        const uint32_t st = sbase + (uint32_t)(i % NSTAGE) * STAGE;

        #pragma unroll
        for (int ks = 0; ks < 4; ++ks) {
            const int c16 = ks * 2 + lm_s;
            uint32_t aF[4][4];
            #pragma unroll
            for (int mt = 0; mt < 4; ++mt) {
                const int row = warp_m + mt * 16 + lm_r;
                const uint32_t ad = st + SA + (uint32_t)row * 128
                                  + (uint32_t)((c16 ^ (row & 7)) * 16);
                ldsm_x4(aF[mt][0], aF[mt][1], aF[mt][2], aF[mt][3], ad);
            }
            #pragma unroll
            for (int g = 0; g < 4; ++g) {
                const int row = warp_n + g * 16 + lm_r;
                const uint32_t bd = st + SB + (uint32_t)row * 128
                                  + (uint32_t)((c16 ^ (row & 7)) * 16);
                uint32_t bf[4];
                ldsm_x4(bf[0], bf[1], bf[2], bf[3], bd);
                #pragma unroll
                for (int sub = 0; sub < 2; ++sub) {
                    const int nt = g * 2 + sub;
                    const uint32_t b0 = sub ? bf[1] : bf[0];
                    const uint32_t b1 = sub ? bf[3] : bf[2];
                    #pragma unroll
                    for (int mt = 0; mt < 4; ++mt)
                        mma_f16(acc[mt][nt], aF[mt], b0, b1);
                }
            }
        }
    }

    // ---- epilogue: pair R/I rows via shfl_xor(4), magnitude, store --------
    const float eps = *eps_p;
    const int r4 = lane >> 2;
    const int c2 = (lane & 3) * 2;
    const bool real_holder = ((r4 & 1) == 0);

    #pragma unroll
    for (int mt = 0; mt < 4; ++mt) {
        const int mbase = m0 + warp_m + mt * 16;
        #pragma unroll
        for (int nt = 0; nt < 8; ++nt) {
            float p[4];
            #pragma unroll
            for (int r = 0; r < 4; ++r)
                p[r] = __shfl_xor_sync(0xffffffffu, acc[mt][nt][r], 4);
            if (real_holder) {
                const int nb = n0 + warp_n + nt * 8 + c2;
                const int f0r = (mbase + r4) >> 1;
                const int f1r = (mbase + r4 + 8) >> 1;
                #pragma unroll
                for (int cc = 0; cc < 2; ++cc) {
                    const int n = nb + cc;
                    float re0 = acc[mt][nt][cc],     im0 = p[cc];
                    float re1 = acc[mt][nt][2 + cc], im1 = p[2 + cc];
                    out[((size_t)b * CUTOFF + f0r) * NFRAMES + n] =
                        sqrtf(fmaf(re0, re0, fmaf(im0, im0, eps)));
                    out[((size_t)b * CUTOFF + f1r) * NFRAMES + n] =
                        sqrtf(fmaf(re1, re1, fmaf(im1, im1, eps)));
                }
            }
        }
    }
}

// ---------------- launch ----------------------------------------------------
extern "C" void kernel_launch(void* const* d_in, const int* in_sizes, int n_in,
                              void* d_out, int out_size)
{
    const float* x     = (const float*)d_in[0];
    const float* basis = (const float*)d_in[1];
    const float* eps   = (const float*)d_in[2];
    float* out = (float*)d_out;

    {
        size_t tot = (size_t)BATCH * XP_LEN / 8;
        pad_half_kernel<<<(unsigned)((tot + 255) / 256), 256>>>(x);
    }
    {
        size_t tot = (size_t)MROWS * FILTER_LEN / 8;
        basis_half_kernel<<<(unsigned)((tot + 255) / 256), 256>>>(basis);
    }
    {
        cudaFuncSetAttribute(stft_mma_kernel,
                             cudaFuncAttributeMaxDynamicSharedMemorySize, DSMEM);
        dim3 grid(16, 9, BATCH);     // y<8: dense GEMM; y==8: fp32 remainder
        stft_mma_kernel<<<grid, 128, DSMEM>>>(x, basis, eps, out);
    }
}

// round 10
// speedup vs baseline: 1.5644x; 1.4038x over previous
#include <cuda_runtime.h>
#include <cuda_fp16.h>
#include <cstdint>
#include <math.h>

#define FILTER_LEN 1024
#define HOP        512
#define CUTOFF     513
#define BATCH      8
#define TLEN       1048576
#define NFRAMES    2049
#define XP_LEN     (TLEN + FILTER_LEN)     // 1049600

#define MROWS   1024                       // interleaved rows: f 0..511 (R,I pairs)
#define BM      128
#define BN      128
#define KC      64                         // fp16 k per chunk (128 B rows)
#define NK      (FILTER_LEN / KC)          // 16

// stage: A(128 rows x 128B) + B(128 rows x 128B); 3 stages, 2 CTAs/SM
#define SA      0
#define SB      16384
#define STAGE   32768
#define NSTAGE  3
#define DSMEM   (NSTAGE * STAGE)           // 96 KB/CTA

#define NREM    (BATCH * (NFRAMES + 512))  // 20488 remainder outputs

// ---------------- device scratch -------------------------------------------
__device__ __align__(128) __half g_xh[(size_t)BATCH * XP_LEN];
__device__ __align__(128) __half g_bh[(size_t)MROWS * FILTER_LEN];

// ---------------- helpers ---------------------------------------------------
__device__ __forceinline__ uint32_t smem_u32(const void* p) {
    uint32_t a;
    asm("{ .reg .u64 t; cvta.to.shared.u64 t, %1; cvt.u32.u64 %0, t; }"
        : "=r"(a) : "l"(p));
    return a;
}
__device__ __forceinline__ void cp_async16(uint32_t dst, const void* src) {
    asm volatile("cp.async.cg.shared.global [%0], [%1], 16;"
                 :: "r"(dst), "l"(src) : "memory");
}
__device__ __forceinline__ void cp_commit() {
    asm volatile("cp.async.commit_group;" ::: "memory");
}
template <int N> __device__ __forceinline__ void cp_wait() {
    asm volatile("cp.async.wait_group %0;" :: "n"(N) : "memory");
}
__device__ __forceinline__ void ldsm_x4(uint32_t& r0, uint32_t& r1,
                                        uint32_t& r2, uint32_t& r3, uint32_t addr) {
    asm volatile("ldmatrix.sync.aligned.m8n8.x4.shared.b16 {%0,%1,%2,%3}, [%4];"
                 : "=r"(r0), "=r"(r1), "=r"(r2), "=r"(r3) : "r"(addr));
}
__device__ __forceinline__ void mma_f16(float* d, const uint32_t* a,
                                        uint32_t b0, uint32_t b1) {
    asm volatile(
        "mma.sync.aligned.m16n8k16.row.col.f32.f16.f16.f32 "
        "{%0,%1,%2,%3}, {%4,%5,%6,%7}, {%8,%9}, {%0,%1,%2,%3};"
        : "+f"(d[0]), "+f"(d[1]), "+f"(d[2]), "+f"(d[3])
        : "r"(a[0]), "r"(a[1]), "r"(a[2]), "r"(a[3]), "r"(b0), "r"(b1));
}
__device__ __forceinline__ uint32_t packh2(float a, float b) {
    __half2 t = __floats2half2_rn(a, b);
    return *reinterpret_cast<uint32_t*>(&t);
}

// ---------------- prep: reflect pad -> fp16 (8 elems/thread) ----------------
__global__ void pad_half_kernel(const float* __restrict__ x) {
    size_t v = (size_t)blockIdx.x * blockDim.x + threadIdx.x;   // 8-elem group
    if (v >= (size_t)BATCH * XP_LEN / 8) return;
    const size_t i0 = v * 8;
    const int b  = (int)(i0 / XP_LEN);
    const int p0 = (int)(i0 % XP_LEN);
    const float* xb = x + (size_t)b * TLEN;
    float e[8];
    #pragma unroll
    for (int q = 0; q < 8; ++q) {
        int j = p0 + q - HOP;
        if (j < 0) j = -j;
        else if (j >= TLEN) j = 2 * TLEN - 2 - j;
        e[q] = xb[j];
    }
    *reinterpret_cast<uint4*>(g_xh + i0) =
        make_uint4(packh2(e[0], e[1]), packh2(e[2], e[3]),
                   packh2(e[4], e[5]), packh2(e[6], e[7]));
}

// interleave basis rows (2f=real, 2f+1=imag) -> fp16
__global__ void basis_half_kernel(const float* __restrict__ basis) {
    size_t v = (size_t)blockIdx.x * blockDim.x + threadIdx.x;   // 8-elem group
    if (v >= (size_t)MROWS * FILTER_LEN / 8) return;
    const size_t i0 = v * 8;
    const int g = (int)(i0 >> 10);
    const int k = (int)(i0 & 1023);
    const int f = g >> 1;
    const int src = (g & 1) ? (f + CUTOFF) : f;
    const float* bs = basis + (size_t)src * FILTER_LEN + k;
    const float4 f0 = *reinterpret_cast<const float4*>(bs);
    const float4 f1 = *reinterpret_cast<const float4*>(bs + 4);
    *reinterpret_cast<uint4*>(g_bh + i0) =
        make_uint4(packh2(f0.x, f0.y), packh2(f0.z, f0.w),
                   packh2(f1.x, f1.y), packh2(f1.z, f1.w));
}

// ---------------- main: fp16 GEMM (y<8) + fp32 remainder (y==8) -------------
__global__ __launch_bounds__(256, 2)
void stft_mma_kernel(const float* __restrict__ x,
                     const float* __restrict__ basis,
                     const float* __restrict__ eps_p,
                     float* __restrict__ out)
{
    const int tid  = threadIdx.x;
    const int wid  = tid >> 5;
    const int lane = tid & 31;

    // ======== remainder: f=512 row + n=2048 column, exact fp32 =============
    if (blockIdx.y == 8) {
        const float eps = *eps_p;
        const int stride = (int)(gridDim.x * gridDim.z) * 8;
        const int wbase = (int)(blockIdx.z * gridDim.x + blockIdx.x) * 8 + wid;
        for (int o = wbase; o < NREM; o += stride) {
            const int b = o / (NFRAMES + 512);
            const int r = o % (NFRAMES + 512);
            int f, n;
            if (r < NFRAMES) { f = 512; n = r; }
            else             { f = r - NFRAMES; n = 2048; }
            const float* bR = basis + (size_t)f * FILTER_LEN;
            const float* bI = basis + (size_t)(f + CUTOFF) * FILTER_LEN;
            const float* xb = x + (size_t)b * TLEN;
            float aR = 0.f, aI = 0.f;
            #pragma unroll 4
            for (int k = lane; k < FILTER_LEN; k += 32) {
                int j = n * HOP + k - HOP;
                if (j < 0) j = -j;
                else if (j >= TLEN) j = 2 * TLEN - 2 - j;
                const float xv = xb[j];
                aR = fmaf(bR[k], xv, aR);
                aI = fmaf(bI[k], xv, aI);
            }
            #pragma unroll
            for (int s = 16; s; s >>= 1) {
                aR += __shfl_xor_sync(0xffffffffu, aR, s);
                aI += __shfl_xor_sync(0xffffffffu, aI, s);
            }
            if (lane == 0)
                out[((size_t)b * CUTOFF + f) * NFRAMES + n] =
                    sqrtf(fmaf(aR, aR, fmaf(aI, aI, eps)));
        }
        return;
    }

    // ======== dense fp16 GEMM: 128x128 tiles, 8 warps, warp 32x64 ==========
    // register-pipelined fragments: ldsm for ks+1 issued before mma of ks
    extern __shared__ char dsm[];
    const uint32_t sbase = smem_u32(dsm);

    const int b  = blockIdx.z;
    const int m0 = blockIdx.y * BM;
    const int n0 = blockIdx.x * BN;

    const int warp_m = (wid >> 1) * 32;    // 0,32,64,96
    const int warp_n = (wid & 1) * 64;     // 0,64

    // loader geometry: A/B each 1024 16B chunks -> 4 rounds of 256 threads
    int l_row[4], l_c16[4]; uint32_t l_soff[4];
    #pragma unroll
    for (int j = 0; j < 4; ++j) {
        int chunk = tid + j * 256;
        l_row[j] = chunk >> 3;
        l_c16[j] = chunk & 7;
        l_soff[j] = (uint32_t)l_row[j] * 128 + (uint32_t)((l_c16[j] ^ (l_row[j] & 7)) * 16);
    }

    const __half* bp = g_bh + (size_t)m0 * FILTER_LEN;
    const __half* xp = g_xh + (size_t)b * XP_LEN + (size_t)n0 * HOP;

    float acc[2][8][4];
    #pragma unroll
    for (int mt = 0; mt < 2; ++mt)
        #pragma unroll
        for (int nt = 0; nt < 8; ++nt)
            #pragma unroll
            for (int r = 0; r < 4; ++r) acc[mt][nt][r] = 0.f;

    const int lm_r = lane & 15;
    const int lm_s = lane >> 4;
    // per-thread base addresses for fragment loads (swizzle applied per c16)
    const uint32_t a_base0 = (uint32_t)(warp_m + lm_r) * 128;        // mt=0 row
    const uint32_t a_base1 = (uint32_t)(warp_m + 16 + lm_r) * 128;   // mt=1 row
    const uint32_t arow7_0 = (uint32_t)((warp_m + lm_r) & 7);
    const uint32_t arow7_1 = (uint32_t)((warp_m + 16 + lm_r) & 7);

    auto load_stage = [&](int i) {
        const uint32_t st = sbase + (uint32_t)(i % NSTAGE) * STAGE;
        const int k0 = i * KC;
        #pragma unroll
        for (int j = 0; j < 4; ++j) {
            cp_async16(st + SA + l_soff[j],
                       bp + (size_t)l_row[j] * FILTER_LEN + k0 + l_c16[j] * 8);
            cp_async16(st + SB + l_soff[j],
                       xp + (size_t)l_row[j] * HOP + k0 + l_c16[j] * 8);
        }
        cp_commit();
    };

    // fragment double buffers
    uint32_t aF[2][2][4];      // [buf][mt][regs]
    uint32_t bF[2][4][4];      // [buf][g][regs]

    auto ldsm_step = [&](int buf, int ks, uint32_t st) {
        const uint32_t c16 = (uint32_t)(ks * 2 + lm_s);
        {
            const uint32_t ad0 = st + SA + a_base0 + ((c16 ^ arow7_0) * 16);
            ldsm_x4(aF[buf][0][0], aF[buf][0][1], aF[buf][0][2], aF[buf][0][3], ad0);
            const uint32_t ad1 = st + SA + a_base1 + ((c16 ^ arow7_1) * 16);
            ldsm_x4(aF[buf][1][0], aF[buf][1][1], aF[buf][1][2], aF[buf][1][3], ad1);
        }
        #pragma unroll
        for (int g = 0; g < 4; ++g) {
            const int row = warp_n + g * 16 + lm_r;
            const uint32_t bd = st + SB + (uint32_t)row * 128
                              + ((c16 ^ (uint32_t)(row & 7)) * 16);
            ldsm_x4(bF[buf][g][0], bF[buf][g][1], bF[buf][g][2], bF[buf][g][3], bd);
        }
    };

    auto mma_step = [&](int buf) {
        #pragma unroll
        for (int g = 0; g < 4; ++g) {
            #pragma unroll
            for (int sub = 0; sub < 2; ++sub) {
                const int nt = g * 2 + sub;
                const uint32_t b0 = sub ? bF[buf][g][1] : bF[buf][g][0];
                const uint32_t b1 = sub ? bF[buf][g][3] : bF[buf][g][2];
                #pragma unroll
                for (int mt = 0; mt < 2; ++mt)
                    mma_f16(acc[mt][nt], aF[buf][mt], b0, b1);
            }
        }
    };

    load_stage(0);
    load_stage(1);

    for (int i = 0; i < NK; ++i) {
        if (i + 1 < NK) cp_wait<1>(); else cp_wait<0>();
        __syncthreads();                    // stage i ready; all warps past i-1
        if (i + 2 < NK) load_stage(i + 2);  // overwrites buffer (i-1)%3: safe

        const uint32_t st = sbase + (uint32_t)(i % NSTAGE) * STAGE;

        ldsm_step(0, 0, st);
        #pragma unroll
        for (int ks = 0; ks < 4; ++ks) {
            if (ks < 3) ldsm_step((ks + 1) & 1, ks + 1, st);  // prefetch next
            mma_step(ks & 1);                                  // 16 indep HMMA
        }
    }

    // ---- epilogue: pair R/I rows via shfl_xor(4), magnitude, store --------
    const float eps = *eps_p;
    const int r4 = lane >> 2;
    const int c2 = (lane & 3) * 2;
    const bool real_holder = ((r4 & 1) == 0);

    #pragma unroll
    for (int mt = 0; mt < 2; ++mt) {
        const int mbase = m0 + warp_m + mt * 16;
        #pragma unroll
        for (int nt = 0; nt < 8; ++nt) {
            float p[4];
            #pragma unroll
            for (int r = 0; r < 4; ++r)
                p[r] = __shfl_xor_sync(0xffffffffu, acc[mt][nt][r], 4);
            if (real_holder) {
                const int nb = n0 + warp_n + nt * 8 + c2;
                const int f0r = (mbase + r4) >> 1;
                const int f1r = (mbase + r4 + 8) >> 1;
                #pragma unroll
                for (int cc = 0; cc < 2; ++cc) {
                    const int n = nb + cc;
                    float re0 = acc[mt][nt][cc],     im0 = p[cc];
                    float re1 = acc[mt][nt][2 + cc], im1 = p[2 + cc];
                    out[((size_t)b * CUTOFF + f0r) * NFRAMES + n] =
                        sqrtf(fmaf(re0, re0, fmaf(im0, im0, eps)));
                    out[((size_t)b * CUTOFF + f1r) * NFRAMES + n] =
                        sqrtf(fmaf(re1, re1, fmaf(im1, im1, eps)));
                }
            }
        }
    }
}

// ---------------- launch ----------------------------------------------------
extern "C" void kernel_launch(void* const* d_in, const int* in_sizes, int n_in,
                              void* d_out, int out_size)
{
    const float* x     = (const float*)d_in[0];
    const float* basis = (const float*)d_in[1];
    const float* eps   = (const float*)d_in[2];
    float* out = (float*)d_out;

    {
        size_t tot = (size_t)BATCH * XP_LEN / 8;
        pad_half_kernel<<<(unsigned)((tot + 255) / 256), 256>>>(x);
    }
    {
        size_t tot = (size_t)MROWS * FILTER_LEN / 8;
        basis_half_kernel<<<(unsigned)((tot + 255) / 256), 256>>>(basis);
    }
    {
        cudaFuncSetAttribute(stft_mma_kernel,
                             cudaFuncAttributeMaxDynamicSharedMemorySize, DSMEM);
        dim3 grid(16, 9, BATCH);     // y<8: dense GEMM; y==8: fp32 remainder
        stft_mma_kernel<<<grid, 256, DSMEM>>>(x, basis, eps, out);
    }
}

// round 11
// speedup vs baseline: 1.6987x; 1.0859x over previous
#include <cuda_runtime.h>
#include <cuda_fp16.h>
#include <cstdint>
#include <math.h>

#define FILTER_LEN 1024
#define HOP        512
#define CUTOFF     513
#define BATCH      8
#define TLEN       1048576
#define NFRAMES    2049
#define NGEMM      2048                    // frames in GEMM (n=2048 -> remainder)
#define KH         512                     // halved K via DFT symmetry

#define BMF     64                         // CTA freq tile
#define BN      128                        // CTA frame tile
#define KC      64                         // fp16 k per chunk (128 B rows)
#define NK      (KH / KC)                  // 8

// stage: AE(64x128B)+AO(64x128B)+BE(128x128B)+BO(128x128B); 2 stages
#define SAE     0
#define SAO     8192
#define SBE     16384
#define SBO     32768
#define STAGE   49152
#define DSMEM   (2 * STAGE)                // 96 KB -> 2 CTAs/SM

#define NREM    (BATCH * (NFRAMES + 512))  // f=512 row + n=2048 col

// ---------------- device scratch -------------------------------------------
__device__ __align__(128) __half g_E [(size_t)BATCH * NGEMM * KH];
__device__ __align__(128) __half g_O [(size_t)BATCH * NGEMM * KH];
__device__ __align__(128) __half g_AE[(size_t)KH * KH];
__device__ __align__(128) __half g_AO[(size_t)KH * KH];

// ---------------- helpers ---------------------------------------------------
__device__ __forceinline__ uint32_t smem_u32(const void* p) {
    uint32_t a;
    asm("{ .reg .u64 t; cvta.to.shared.u64 t, %1; cvt.u32.u64 %0, t; }"
        : "=r"(a) : "l"(p));
    return a;
}
__device__ __forceinline__ void cp_async16(uint32_t dst, const void* src) {
    asm volatile("cp.async.cg.shared.global [%0], [%1], 16;"
                 :: "r"(dst), "l"(src) : "memory");
}
__device__ __forceinline__ void cp_commit() {
    asm volatile("cp.async.commit_group;" ::: "memory");
}
template <int N> __device__ __forceinline__ void cp_wait() {
    asm volatile("cp.async.wait_group %0;" :: "n"(N) : "memory");
}
__device__ __forceinline__ void ldsm_x4(uint32_t& r0, uint32_t& r1,
                                        uint32_t& r2, uint32_t& r3, uint32_t addr) {
    asm volatile("ldmatrix.sync.aligned.m8n8.x4.shared.b16 {%0,%1,%2,%3}, [%4];"
                 : "=r"(r0), "=r"(r1), "=r"(r2), "=r"(r3) : "r"(addr));
}
__device__ __forceinline__ void mma_f16(float* d, const uint32_t* a,
                                        uint32_t b0, uint32_t b1) {
    asm volatile(
        "mma.sync.aligned.m16n8k16.row.col.f32.f16.f16.f32 "
        "{%0,%1,%2,%3}, {%4,%5,%6,%7}, {%8,%9}, {%0,%1,%2,%3};"
        : "+f"(d[0]), "+f"(d[1]), "+f"(d[2]), "+f"(d[3])
        : "r"(a[0]), "r"(a[1]), "r"(a[2]), "r"(a[3]), "r"(b0), "r"(b1));
}
__device__ __forceinline__ uint32_t packh2(float a, float b) {
    __half2 t = __floats2half2_rn(a, b);
    return *reinterpret_cast<uint32_t*>(&t);
}
__device__ __forceinline__ int reflect_idx(int j) {
    if (j < 0) j = -j;
    else if (j >= TLEN) j = 2 * TLEN - 2 - j;
    return j;
}

// ---------------- prep 1: E/O construction ----------------------------------
// E[b][n][j]: j=0 -> x-center; j>=1 -> xw[j]+xw[1024-j]. O analogous (minus), O[.][0]=0.
__global__ void eo_kernel(const float* __restrict__ x) {
    size_t v = (size_t)blockIdx.x * blockDim.x + threadIdx.x;   // 8-j group
    const size_t total = (size_t)BATCH * NGEMM * (KH / 8);
    if (v >= total) return;
    const int jg = (int)(v % (KH / 8));
    const int n  = (int)((v / (KH / 8)) % NGEMM);
    const int b  = (int)(v / ((size_t)(KH / 8) * NGEMM));
    const float* xb = x + (size_t)b * TLEN;
    const int j0 = jg * 8;

    float e[8], o[8];
    if (n >= 1 && n <= 2046) {
        // fast path: no reflection
        const float* asc = xb + (size_t)n * HOP - 512 + j0;       // x[i1], ascending
        const int Cdesc = n * HOP + 512 - j0;                     // x[i2] = x[Cdesc - t]
        #pragma unroll
        for (int t = 0; t < 8; ++t) {
            const float x1 = asc[t];
            const float x2 = xb[Cdesc - t];
            e[t] = x1 + x2;
            o[t] = x1 - x2;
        }
    } else {
        #pragma unroll
        for (int t = 0; t < 8; ++t) {
            const int j = j0 + t;
            const float x1 = xb[reflect_idx(n * HOP + j - 512)];
            const float x2 = xb[reflect_idx(n * HOP + 512 - j)];
            e[t] = x1 + x2;
            o[t] = x1 - x2;
        }
    }
    if (jg == 0) {                         // j=0 special slots
        e[0] = xb[reflect_idx(n * HOP)];   // window center sample
        o[0] = 0.f;
    }
    const size_t base = ((size_t)b * NGEMM + n) * KH + j0;
    *reinterpret_cast<uint4*>(g_E + base) =
        make_uint4(packh2(e[0], e[1]), packh2(e[2], e[3]),
                   packh2(e[4], e[5]), packh2(e[6], e[7]));
    *reinterpret_cast<uint4*>(g_O + base) =
        make_uint4(packh2(o[0], o[1]), packh2(o[2], o[3]),
                   packh2(o[4], o[5]), packh2(o[6], o[7]));
}

// ---------------- prep 2: symmetric/antisymmetric basis halves --------------
__global__ void basis_eo_kernel(const float* __restrict__ basis) {
    size_t v = (size_t)blockIdx.x * blockDim.x + threadIdx.x;   // 8-j group
    if (v >= (size_t)KH * (KH / 8)) return;
    const int jg = (int)(v % (KH / 8));
    const int f  = (int)(v / (KH / 8));
    const int j0 = jg * 8;
    const float* bR = basis + (size_t)f * FILTER_LEN;
    const float* bI = basis + (size_t)(CUTOFF + f) * FILTER_LEN;
    float ae[8], ao[8];
    #pragma unroll
    for (int t = 0; t < 8; ++t) {
        const int j = j0 + t;
        if (j == 0) {
            ae[t] = bR[512];
            ao[t] = 0.f;
        } else {
            ae[t] = 0.5f * (bR[j] + bR[FILTER_LEN - j]);
            ao[t] = 0.5f * (bI[j] - bI[FILTER_LEN - j]);
        }
    }
    const size_t base = (size_t)f * KH + j0;
    *reinterpret_cast<uint4*>(g_AE + base) =
        make_uint4(packh2(ae[0], ae[1]), packh2(ae[2], ae[3]),
                   packh2(ae[4], ae[5]), packh2(ae[6], ae[7]));
    *reinterpret_cast<uint4*>(g_AO + base) =
        make_uint4(packh2(ao[0], ao[1]), packh2(ao[2], ao[3]),
                   packh2(ao[4], ao[5]), packh2(ao[6], ao[7]));
}

// ---------------- main: dual fp16 GEMM + fused magnitude --------------------
__global__ __launch_bounds__(256, 2)
void stft_mma_kernel(const float* __restrict__ x,
                     const float* __restrict__ basis,
                     const float* __restrict__ eps_p,
                     float* __restrict__ out)
{
    const int tid  = threadIdx.x;
    const int wid  = tid >> 5;
    const int lane = tid & 31;

    // ======== remainder: f=512 row + n=2048 column, exact fp32 =============
    if (blockIdx.y == 8) {
        const float eps = *eps_p;
        const int stride = (int)(gridDim.x * gridDim.z) * 8;
        const int wbase = (int)(blockIdx.z * gridDim.x + blockIdx.x) * 8 + wid;
        for (int o = wbase; o < NREM; o += stride) {
            const int b = o / (NFRAMES + 512);
            const int r = o % (NFRAMES + 512);
            int f, n;
            if (r < NFRAMES) { f = 512; n = r; }
            else             { f = r - NFRAMES; n = 2048; }
            const float* bR = basis + (size_t)f * FILTER_LEN;
            const float* bI = basis + (size_t)(f + CUTOFF) * FILTER_LEN;
            const float* xb = x + (size_t)b * TLEN;
            float aR = 0.f, aI = 0.f;
            #pragma unroll 4
            for (int k = lane; k < FILTER_LEN; k += 32) {
                const int j = reflect_idx(n * HOP + k - 512);
                const float xv = xb[j];
                aR = fmaf(bR[k], xv, aR);
                aI = fmaf(bI[k], xv, aI);
            }
            #pragma unroll
            for (int s = 16; s; s >>= 1) {
                aR += __shfl_xor_sync(0xffffffffu, aR, s);
                aI += __shfl_xor_sync(0xffffffffu, aI, s);
            }
            if (lane == 0)
                out[((size_t)b * CUTOFF + f) * NFRAMES + n] =
                    sqrtf(fmaf(aR, aR, fmaf(aI, aI, eps)));
        }
        return;
    }

    // ======== dense dual GEMM: 64f x 128n tile, warp 32x32, K=512 ==========
    extern __shared__ char dsm[];
    const uint32_t sbase = smem_u32(dsm);

    const int b  = blockIdx.z;
    const int m0 = blockIdx.y * BMF;       // freq tile base
    const int n0 = blockIdx.x * BN;

    const int warp_f = (wid >> 2) * 32;    // 0,32
    const int warp_n = (wid & 3) * 32;     // 0,32,64,96

    // loader: per stage AE/AO 512 chunks (2 rounds), BE/BO 1024 (4 rounds)
    int a_row[2], a_c16[2]; uint32_t a_soff[2];
    #pragma unroll
    for (int j = 0; j < 2; ++j) {
        int chunk = tid + j * 256;
        a_row[j] = chunk >> 3;
        a_c16[j] = chunk & 7;
        a_soff[j] = (uint32_t)a_row[j] * 128 + (uint32_t)((a_c16[j] ^ (a_row[j] & 7)) * 16);
    }
    int b_row[4], b_c16[4]; uint32_t b_soff[4];
    #pragma unroll
    for (int j = 0; j < 4; ++j) {
        int chunk = tid + j * 256;
        b_row[j] = chunk >> 3;
        b_c16[j] = chunk & 7;
        b_soff[j] = (uint32_t)b_row[j] * 128 + (uint32_t)((b_c16[j] ^ (b_row[j] & 7)) * 16);
    }

    const __half* aE = g_AE + (size_t)m0 * KH;
    const __half* aO = g_AO + (size_t)m0 * KH;
    const __half* bE = g_E + ((size_t)b * NGEMM + n0) * KH;
    const __half* bO = g_O + ((size_t)b * NGEMM + n0) * KH;

    float accR[2][4][4], accI[2][4][4];
    #pragma unroll
    for (int mt = 0; mt < 2; ++mt)
        #pragma unroll
        for (int nt = 0; nt < 4; ++nt)
            #pragma unroll
            for (int r = 0; r < 4; ++r) { accR[mt][nt][r] = 0.f; accI[mt][nt][r] = 0.f; }

    const int lm_r = lane & 15;
    const int lm_s = lane >> 4;

    auto load_stage = [&](int i) {
        const uint32_t st = sbase + (uint32_t)(i & 1) * STAGE;
        const int k0 = i * KC;
        #pragma unroll
        for (int j = 0; j < 2; ++j) {
            const size_t off = (size_t)a_row[j] * KH + k0 + a_c16[j] * 8;
            cp_async16(st + SAE + a_soff[j], aE + off);
            cp_async16(st + SAO + a_soff[j], aO + off);
        }
        #pragma unroll
        for (int j = 0; j < 4; ++j) {
            const size_t off = (size_t)b_row[j] * KH + k0 + b_c16[j] * 8;
            cp_async16(st + SBE + b_soff[j], bE + off);
            cp_async16(st + SBO + b_soff[j], bO + off);
        }
        cp_commit();
    };

    load_stage(0);

    for (int i = 0; i < NK; ++i) {
        if (i + 1 < NK) { load_stage(i + 1); cp_wait<1>(); }
        else            { cp_wait<0>(); }
        __syncthreads();

        const uint32_t st = sbase + (uint32_t)(i & 1) * STAGE;

        #pragma unroll
        for (int ks = 0; ks < 4; ++ks) {
            const int c16 = ks * 2 + lm_s;
            uint32_t fE[2][4], fO[2][4];
            #pragma unroll
            for (int mt = 0; mt < 2; ++mt) {
                const int row = warp_f + mt * 16 + lm_r;
                const uint32_t sw = (uint32_t)((c16 ^ (row & 7)) * 16);
                ldsm_x4(fE[mt][0], fE[mt][1], fE[mt][2], fE[mt][3],
                        st + SAE + (uint32_t)row * 128 + sw);
                ldsm_x4(fO[mt][0], fO[mt][1], fO[mt][2], fO[mt][3],
                        st + SAO + (uint32_t)row * 128 + sw);
            }
            #pragma unroll
            for (int g = 0; g < 2; ++g) {
                const int row = warp_n + g * 16 + lm_r;
                const uint32_t sw = (uint32_t)((c16 ^ (row & 7)) * 16);
                uint32_t hE[4], hO[4];
                ldsm_x4(hE[0], hE[1], hE[2], hE[3],
                        st + SBE + (uint32_t)row * 128 + sw);
                ldsm_x4(hO[0], hO[1], hO[2], hO[3],
                        st + SBO + (uint32_t)row * 128 + sw);
                #pragma unroll
                for (int sub = 0; sub < 2; ++sub) {
                    const int nt = g * 2 + sub;
                    const uint32_t e0 = sub ? hE[1] : hE[0];
                    const uint32_t e1 = sub ? hE[3] : hE[2];
                    const uint32_t o0 = sub ? hO[1] : hO[0];
                    const uint32_t o1 = sub ? hO[3] : hO[2];
                    #pragma unroll
                    for (int mt = 0; mt < 2; ++mt) {
                        mma_f16(accR[mt][nt], fE[mt], e0, e1);
                        mma_f16(accI[mt][nt], fO[mt], o0, o1);
                    }
                }
            }
        }
        __syncthreads();
    }

    // ---- epilogue: magnitude directly (R and I co-resident), store --------
    const float eps = *eps_p;
    const int r4 = lane >> 2;
    const int c2 = (lane & 3) * 2;

    #pragma unroll
    for (int mt = 0; mt < 2; ++mt) {
        const int fbase = m0 + warp_f + mt * 16;
        #pragma unroll
        for (int nt = 0; nt < 4; ++nt) {
            const int n = n0 + warp_n + nt * 8 + c2;
            const int f0 = fbase + r4;
            const int f1 = f0 + 8;
            #pragma unroll
            for (int cc = 0; cc < 2; ++cc) {
                const float r0 = accR[mt][nt][cc],     i0 = accI[mt][nt][cc];
                const float r1 = accR[mt][nt][2 + cc], i1 = accI[mt][nt][2 + cc];
                out[((size_t)b * CUTOFF + f0) * NFRAMES + n + cc] =
                    sqrtf(fmaf(r0, r0, fmaf(i0, i0, eps)));
                out[((size_t)b * CUTOFF + f1) * NFRAMES + n + cc] =
                    sqrtf(fmaf(r1, r1, fmaf(i1, i1, eps)));
            }
        }
    }
}

// ---------------- launch ----------------------------------------------------
extern "C" void kernel_launch(void* const* d_in, const int* in_sizes, int n_in,
                              void* d_out, int out_size)
{
    const float* x     = (const float*)d_in[0];
    const float* basis = (const float*)d_in[1];
    const float* eps   = (const float*)d_in[2];
    float* out = (float*)d_out;

    {
        size_t tot = (size_t)BATCH * NGEMM * (KH / 8);
        eo_kernel<<<(unsigned)((tot + 255) / 256), 256>>>(x);
    }
    {
        size_t tot = (size_t)KH * (KH / 8);
        basis_eo_kernel<<<(unsigned)((tot + 255) / 256), 256>>>(basis);
    }
    {
        cudaFuncSetAttribute(stft_mma_kernel,
                             cudaFuncAttributeMaxDynamicSharedMemorySize, DSMEM);
        dim3 grid(16, 9, BATCH);     // y<8: dual GEMM; y==8: fp32 remainder
        stft_mma_kernel<<<grid, 256, DSMEM>>>(x, basis, eps, out);
    }
}